// round 12
// baseline (speedup 1.0000x reference)
#include <cuda_runtime.h>
#include <cstdint>

#define NB   2048
#define INS  512
#define SEQL 128
#define NH   12
#define NOUT 3

__device__ __forceinline__ unsigned long long fma2(unsigned long long a,
                                                   unsigned long long b,
                                                   unsigned long long c) {
    unsigned long long d;
    asm("fma.rn.f32x2 %0, %1, %2, %3;" : "=l"(d) : "l"(a), "l"(b), "l"(c));
    return d;
}
__device__ __forceinline__ unsigned long long pk2(float f) {
    unsigned long long u;
    asm("mov.b64 %0, {%1, %1};" : "=l"(u) : "f"(f));
    return u;
}
__device__ __forceinline__ float ftanh(float x) {
    float e = __expf(2.0f * x);
    return 1.0f - __fdividef(2.0f, e + 1.0f);
}

// ---------------------------------------------------------------------------
// ONE fused kernel, one block per batch (grid 2048, 128 thr).
// Phase 1: warp w computes pre[s, 0..11] for s in [32w, 32w+32); lane owns
//   one s. e = emb[x_i][s]: coalesced 128B LDG.32 per warp-i; weights from
//   24KB smem as (w[2k],w[2k+1]) f32x2 pairs (3 broadcast LDS.128/i);
//   6 FFMA2/i/lane. Result -> 6KB smem; the 25MB gmem pre round-trip that
//   held scan at DRAM latency (R10/R11: 32-38us, occ 10%) is GONE.
// Phase 2: warp 0 scans the 128-step recurrence from smem (LDS 29cyc);
//   warps 2-3 concurrently compute h_bwd (e127 smem + L1-hot w_ih_r gmem).
// Phase 3: FC epilogue on warp 0.
// Low regs + 33KB smem -> 6 blocks/SM; other blocks' phase-1 fma fills this
// block's phase-2 bubbles.
// ---------------------------------------------------------------------------
extern "C" __global__ void __launch_bounds__(128, 6)
fused_kernel(const int* __restrict__ x, const float* __restrict__ emb,
             const float* __restrict__ wih,
             const float* __restrict__ wir, const float* __restrict__ bir,
             const float* __restrict__ bhr,
             const float* __restrict__ whh, const float* __restrict__ bih,
             const float* __restrict__ bhh, const float* __restrict__ fcw,
             const float* __restrict__ fcb, float* __restrict__ out) {
    __shared__ float2 w2[INS * 6];                   // 24 KB fwd weight pairs
    __shared__ __align__(16) float pre_s[SEQL * NH]; // 6 KB
    __shared__ float e127[INS];                      // 2 KB
    __shared__ float hbpart[2][NH];

    const int tid = threadIdx.x;
    const int warp = tid >> 5;
    const int lane = tid & 31;
    const int b = blockIdx.x;

    // ---- stage weights + e127 ----
    for (int t = tid; t < INS * 6; t += 128) {
        int i = t & (INS - 1);
        int k = t >> 9;                              // 0..5
        w2[i * 6 + k] = make_float2(wih[(2 * k) * INS + i],
                                    wih[(2 * k + 1) * INS + i]);
    }
    for (int t = tid; t < INS; t += 128)
        e127[t] = emb[(size_t)t * SEQL + (SEQL - 1)];
    __syncthreads();

    // ================= Phase 1: pre into smem =================
    {
        const int s = warp * 32 + lane;
        const float* es = emb + s;
        const int4* xg = (const int4*)(x + (size_t)b * INS);  // 128 groups

        unsigned long long acc[6];
#pragma unroll
        for (int k = 0; k < 6; k++) acc[k] = 0ull;

        float eA[4], eB[4];
        int4 qB_cur, qA_next, qB_next, qA_nn;

#define LOADE(buf, q)                                                         \
    do {                                                                      \
        buf[0] = es[(unsigned)(q).x << 7];                                    \
        buf[1] = es[(unsigned)(q).y << 7];                                    \
        buf[2] = es[(unsigned)(q).z << 7];                                    \
        buf[3] = es[(unsigned)(q).w << 7];                                    \
    } while (0)

#define COMP4(buf, bi)                                                        \
    do {                                                                      \
        _Pragma("unroll")                                                     \
        for (int u = 0; u < 4; u++) {                                         \
            unsigned long long ep = pk2(buf[u]);                              \
            const ulonglong2* wv =                                            \
                (const ulonglong2*)(w2 + (unsigned)((bi) + u) * 6);           \
            ulonglong2 wA = wv[0], wB = wv[1], wC = wv[2];                    \
            acc[0] = fma2(ep, wA.x, acc[0]);                                  \
            acc[1] = fma2(ep, wA.y, acc[1]);                                  \
            acc[2] = fma2(ep, wB.x, acc[2]);                                  \
            acc[3] = fma2(ep, wB.y, acc[3]);                                  \
            acc[4] = fma2(ep, wC.x, acc[4]);                                  \
            acc[5] = fma2(ep, wC.y, acc[5]);                                  \
        }                                                                     \
    } while (0)

        {
            int4 qA0 = __ldg(xg + 0);
            qB_cur  = __ldg(xg + 1);
            qA_next = __ldg(xg + 2);
            LOADE(eA, qA0);
        }
#pragma unroll 1
        for (int io = 0; io < INS; io += 8) {
            const int j = io >> 2;
            LOADE(eB, qB_cur);
            qB_next = __ldg(xg + ((j + 3 < 128) ? j + 3 : 0));
            COMP4(eA, io);
            LOADE(eA, qA_next);
            qA_nn = __ldg(xg + ((j + 4 < 128) ? j + 4 : 0));
            COMP4(eB, io + 4);
            qB_cur = qB_next;
            qA_next = qA_nn;
        }
#undef LOADE
#undef COMP4

        // acc[k] = (pre[s,2k], pre[s,2k+1]) -> 48B row, 16B-aligned
        ulonglong2* d = (ulonglong2*)(pre_s + s * NH);
        ulonglong2 v;
        v.x = acc[0]; v.y = acc[1]; d[0] = v;
        v.x = acc[2]; v.y = acc[3]; d[1] = v;
        v.x = acc[4]; v.y = acc[5]; d[2] = v;
    }
    __syncthreads();

    // ================= Phase 2: scan (warp 0) || h_bwd (warps 2,3) ========
    const int hl = lane & 15;
    const int hc = hl < NH ? hl : 0;
    float h = 0.f;

    if (warp == 0) {
        float wrow[NH];
#pragma unroll
        for (int j = 0; j < NH; j++) wrow[j] = whh[hc * NH + j];
        const float bias = bih[hc] + bhh[hc];

        float p0 = pre_s[hc], p1 = pre_s[NH + hc];
#pragma unroll 4
        for (int s = 0; s < SEQL; s++) {
            float pb = p0 + bias;
            p0 = p1;
            int sl = (s + 2 < SEQL) ? (s + 2) : (SEQL - 1);
            p1 = pre_s[sl * NH + hc];

            float v[NH];
#pragma unroll
            for (int j = 0; j < NH; j++)
                v[j] = __shfl_sync(0xffffffffu, h, j, 16);
            float t0 = fmaf(v[0], wrow[0], pb);
            float t1 = v[1] * wrow[1];
            float t2 = v[2] * wrow[2];
#pragma unroll
            for (int j = 3; j < NH; j += 3) {
                t0 = fmaf(v[j    ], wrow[j    ], t0);
                t1 = fmaf(v[j + 1], wrow[j + 1], t1);
                t2 = fmaf(v[j + 2], wrow[j + 2], t2);
            }
            h = ftanh(t0 + t1 + t2);
        }
    } else if (warp >= 2) {
        // h_bwd partial: 64 threads cover i = wt + 64k
        const int wt = tid - 64;              // 0..63
        const int* xrow = x + (size_t)b * INS;
        float a2[NH];
#pragma unroll
        for (int j = 0; j < NH; j++) a2[j] = 0.f;
#pragma unroll 1
        for (int k = 0; k < 8; k++) {
            const int i = wt + 64 * k;
            const float e = e127[__ldg(xrow + i)];
#pragma unroll
            for (int j = 0; j < NH; j++)
                a2[j] = fmaf(e, __ldg(wir + j * INS + i), a2[j]);
        }
#pragma unroll
        for (int j = 0; j < NH; j++) {
#pragma unroll
            for (int o = 16; o; o >>= 1)
                a2[j] += __shfl_xor_sync(0xffffffffu, a2[j], o);
        }
        if (lane == 0) {
#pragma unroll
            for (int j = 0; j < NH; j++) hbpart[warp - 2][j] = a2[j];
        }
    }
    __syncthreads();

    // ================= Phase 3: FC epilogue (warp 0, lanes 0-15) ==========
    if (warp == 0) {
        float v[NH];
#pragma unroll
        for (int j = 0; j < NH; j++)
            v[j] = __shfl_sync(0xffffffffu, h, j, 16);
        if (hl < NOUT && lane < 16) {
            float o = fcb[hl];
#pragma unroll
            for (int j = 0; j < NH; j++)
                o = fmaf(v[j], fcw[hl * 2 * NH + j], o);
#pragma unroll
            for (int j = 0; j < NH; j++) {
                float hbj = ftanh(hbpart[0][j] + hbpart[1][j] +
                                  bir[j] + bhr[j]);
                o = fmaf(hbj, fcw[hl * 2 * NH + NH + j], o);
            }
            out[b * NOUT + hl] = o;
        }
    }
}

// ---------------------------------------------------------------------------
extern "C" void kernel_launch(void* const* d_in, const int* in_sizes, int n_in,
                              void* d_out, int out_size) {
    const int*   x      = (const int*)  d_in[0];
    const float* emb    = (const float*)d_in[1];
    const float* w_ih_f = (const float*)d_in[2];
    const float* w_hh_f = (const float*)d_in[3];
    const float* b_ih_f = (const float*)d_in[4];
    const float* b_hh_f = (const float*)d_in[5];
    const float* w_ih_r = (const float*)d_in[6];
    // d_in[7] = w_hh_r (unused: reference consumes only the one-step reverse state)
    const float* b_ih_r = (const float*)d_in[8];
    const float* b_hh_r = (const float*)d_in[9];
    const float* fc_w   = (const float*)d_in[10];
    const float* fc_b   = (const float*)d_in[11];
    float* out = (float*)d_out;

    fused_kernel<<<NB, 128>>>(x, emb, w_ih_f,
                              w_ih_r, b_ih_r, b_hh_r,
                              w_hh_f, b_ih_f, b_hh_f, fc_w, fc_b, out);
}

// round 14
// speedup vs baseline: 2.5526x; 2.5526x over previous
#include <cuda_runtime.h>
#include <cstdint>

#define NB   2048
#define INS  512
#define SEQL 128
#define NH   12
#define NOUT 3

// scratch (allocation-free contract: __device__ globals)
__device__ float g_pre0[(size_t)NB * SEQL * NH];   // [b][s][h], K-half 0
__device__ float g_pre1[(size_t)NB * SEQL * NH];   // [b][s][h], K-half 1

__device__ __forceinline__ unsigned long long fma2(unsigned long long a,
                                                   unsigned long long b,
                                                   unsigned long long c) {
    unsigned long long d;
    asm("fma.rn.f32x2 %0, %1, %2, %3;" : "=l"(d) : "l"(a), "l"(b), "l"(c));
    return d;
}
__device__ __forceinline__ unsigned long long pk2(float f) {
    unsigned long long u;
    asm("mov.b64 %0, {%1, %1};" : "=l"(u) : "f"(f));
    return u;
}
__device__ __forceinline__ float ftanh(float x) {
    float e = __expf(2.0f * x);
    return 1.0f - __fdividef(2.0f, e + 1.0f);
}

// ---------------------------------------------------------------------------
// Kernel 1: pre_y[b,s,h] = sum_{i in K-half y} emb[x[b,i], s] * w_ih_f[h,i]
// (R10 exactly: measured 67us. Warp per batch, lane owns 4 s, 12KB K-half
// weight smem, 4-i ping-pong float4 e-prefetch, 32-bit gather addressing.)
// ---------------------------------------------------------------------------
extern "C" __global__ void __launch_bounds__(128, 5)
pre_kernel(const int* __restrict__ x, const float* __restrict__ emb,
           const float* __restrict__ wih) {
    __shared__ float2 w2[256 * 6];   // 12 KB: this K-half only

    const int tid = threadIdx.x;
    const int y = blockIdx.y;            // K-half
    const int ibase = y * 256;

    for (int t = tid; t < 256 * 6; t += 128) {
        int il = t & 255;
        int k = t >> 8;                  // 0..5
        w2[il * 6 + k] = make_float2(wih[(2 * k) * INS + ibase + il],
                                     wih[(2 * k + 1) * INS + ibase + il]);
    }
    __syncthreads();

    const int warp = tid >> 5;
    const int lane = tid & 31;
    const int b = blockIdx.x * 4 + warp;
    const int4* xg = (const int4*)(x + (size_t)b * INS) + y * 64;
    const float* ebase = emb + 4 * lane;

    unsigned long long aa[4][6];         // [s-slot][h-pair]
#pragma unroll
    for (int sp = 0; sp < 4; sp++)
#pragma unroll
        for (int k = 0; k < 6; k++) aa[sp][k] = 0ull;

    float4 eA[4], eB[4];
    int4 qB_cur, qA_next, qB_next, qA_nn;

#define LOADE(buf, q)                                                         \
    do {                                                                      \
        buf[0] = *(const float4*)(ebase + ((unsigned)(q).x << 7));            \
        buf[1] = *(const float4*)(ebase + ((unsigned)(q).y << 7));            \
        buf[2] = *(const float4*)(ebase + ((unsigned)(q).z << 7));            \
        buf[3] = *(const float4*)(ebase + ((unsigned)(q).w << 7));            \
    } while (0)

#define COMPUTE4(buf, bi)                                                     \
    do {                                                                      \
        _Pragma("unroll")                                                     \
        for (int u = 0; u < 4; u++) {                                         \
            unsigned long long p0 = pk2(buf[u].x);                            \
            unsigned long long p1 = pk2(buf[u].y);                            \
            unsigned long long p2 = pk2(buf[u].z);                            \
            unsigned long long p3 = pk2(buf[u].w);                            \
            const ulonglong2* wv =                                            \
                (const ulonglong2*)(w2 + (unsigned)((bi) + u) * 6);           \
            ulonglong2 wA = wv[0], wB = wv[1], wC = wv[2];                    \
            aa[0][0] = fma2(p0, wA.x, aa[0][0]);                              \
            aa[1][0] = fma2(p1, wA.x, aa[1][0]);                              \
            aa[2][0] = fma2(p2, wA.x, aa[2][0]);                              \
            aa[3][0] = fma2(p3, wA.x, aa[3][0]);                              \
            aa[0][1] = fma2(p0, wA.y, aa[0][1]);                              \
            aa[1][1] = fma2(p1, wA.y, aa[1][1]);                              \
            aa[2][1] = fma2(p2, wA.y, aa[2][1]);                              \
            aa[3][1] = fma2(p3, wA.y, aa[3][1]);                              \
            aa[0][2] = fma2(p0, wB.x, aa[0][2]);                              \
            aa[1][2] = fma2(p1, wB.x, aa[1][2]);                              \
            aa[2][2] = fma2(p2, wB.x, aa[2][2]);                              \
            aa[3][2] = fma2(p3, wB.x, aa[3][2]);                              \
            aa[0][3] = fma2(p0, wB.y, aa[0][3]);                              \
            aa[1][3] = fma2(p1, wB.y, aa[1][3]);                              \
            aa[2][3] = fma2(p2, wB.y, aa[2][3]);                              \
            aa[3][3] = fma2(p3, wB.y, aa[3][3]);                              \
            aa[0][4] = fma2(p0, wC.x, aa[0][4]);                              \
            aa[1][4] = fma2(p1, wC.x, aa[1][4]);                              \
            aa[2][4] = fma2(p2, wC.x, aa[2][4]);                              \
            aa[3][4] = fma2(p3, wC.x, aa[3][4]);                              \
            aa[0][5] = fma2(p0, wC.y, aa[0][5]);                              \
            aa[1][5] = fma2(p1, wC.y, aa[1][5]);                              \
            aa[2][5] = fma2(p2, wC.y, aa[2][5]);                              \
            aa[3][5] = fma2(p3, wC.y, aa[3][5]);                              \
        }                                                                     \
    } while (0)

    {
        int4 qA0 = __ldg(xg + 0);
        qB_cur  = __ldg(xg + 1);
        qA_next = __ldg(xg + 2);
        LOADE(eA, qA0);
    }

#pragma unroll 1
    for (int io = 0; io < 256; io += 8) {
        const int j = io >> 2;
        LOADE(eB, qB_cur);
        qB_next = __ldg(xg + ((j + 3 < 64) ? j + 3 : 0));
        COMPUTE4(eA, io);
        LOADE(eA, qA_next);
        qA_nn = __ldg(xg + ((j + 4 < 64) ? j + 4 : 0));
        COMPUTE4(eB, io + 4);
        qB_cur = qB_next;
        qA_next = qA_nn;
    }
#undef LOADE
#undef COMPUTE4

    float* dstb = (y == 0 ? g_pre0 : g_pre1) +
                  ((size_t)b * SEQL + 4 * lane) * NH;
#pragma unroll
    for (int sp = 0; sp < 4; sp++) {
        ulonglong2* d = (ulonglong2*)(dstb + (size_t)sp * NH);
        ulonglong2 v;
        v.x = aa[sp][0]; v.y = aa[sp][1]; d[0] = v;
        v.x = aa[sp][2]; v.y = aa[sp][3]; d[1] = v;
        v.x = aa[sp][4]; v.y = aa[sp][5]; d[2] = v;
    }
}

// ---------------------------------------------------------------------------
// Kernel 2: scan + fused h_bwd + FC epilogue, with COOPERATIVE SMEM STAGING.
// R11 was request-rate bound (906GB/s, scalar LDG.32, 48B useful/warp-req).
// Now: per 8-s chunk, the 128-thread block stages the next chunk for all 8
// batches (2 halves x 8 b x 384 contiguous B) with 3 coalesced LDG.128 per
// thread into a smem double buffer; the 8 recurrence steps (~700cyc) cover
// the load latency. 16 lanes per batch, shfl width 16.
// ---------------------------------------------------------------------------
extern "C" __global__ void __launch_bounds__(128)
scan_kernel(const int* __restrict__ x, const float* __restrict__ emb,
            const float* __restrict__ wir, const float* __restrict__ bir,
            const float* __restrict__ bhr,
            const float* __restrict__ whh, const float* __restrict__ bih,
            const float* __restrict__ bhh, const float* __restrict__ fcw,
            const float* __restrict__ fcb, float* __restrict__ out) {
    __shared__ float ws[NH * INS];            // 24 KB  w_ih_r [h][i]
    __shared__ float e127[INS];               // 2 KB   emb[:,127]
    __shared__ __align__(16) float stg[2][2][8 * 96]; // 12 KB [buf][half][b*96]

    const int tid = threadIdx.x;
    for (int t = tid; t < NH * INS; t += 128) ws[t] = wir[t];
    for (int t = tid; t < INS; t += 128)
        e127[t] = emb[(size_t)t * SEQL + (SEQL - 1)];

    const int bslot = tid >> 4;
    const int b = blockIdx.x * 8 + bslot;
    const int hl = tid & 15;
    const int hc = hl < NH ? hl : 0;
    const int* xrow = x + (size_t)b * INS;

    // staging-thread mapping: thread covers float4 indices tid, tid+128, tid+256
    // idx in [0,384): half = idx/192, r = idx%192, sb = r/24, off = r%24
    const float* srcbase[2] = {g_pre0, g_pre1};
    float4 ld[3];
#define STAGE_LOAD(chunk)                                                     \
    do {                                                                      \
        _Pragma("unroll")                                                     \
        for (int q = 0; q < 3; q++) {                                         \
            int idx = tid + 128 * q;                                          \
            int half = idx / 192, r = idx - half * 192;                       \
            int sb = r / 24, off = r - sb * 24;                               \
            const float* src = srcbase[half] +                                \
                ((size_t)(blockIdx.x * 8 + sb) * SEQL + (chunk) * 8) * NH;    \
            ld[q] = *(const float4*)(src + off * 4);                          \
        }                                                                     \
    } while (0)
#define STAGE_STORE(p)                                                        \
    do {                                                                      \
        _Pragma("unroll")                                                     \
        for (int q = 0; q < 3; q++) {                                         \
            int idx = tid + 128 * q;                                          \
            int half = idx / 192, r = idx - half * 192;                       \
            int sb = r / 24, off = r - sb * 24;                               \
            *(float4*)(&stg[p][half][sb * 96 + off * 4]) = ld[q];             \
        }                                                                     \
    } while (0)

    // prologue: stage chunk 0 into buf 0 (overlaps ws/e127 staging)
    STAGE_LOAD(0);
    STAGE_STORE(0);
    __syncthreads();

    // ---- fused h_bwd (lane hl covers i = hl + 16k) ----
    float hb;
    {
        float acc[NH];
#pragma unroll
        for (int h = 0; h < NH; h++) acc[h] = 0.f;
#pragma unroll 1
        for (int k = 0; k < 32; k += 8) {
            int idv[8];
#pragma unroll
            for (int j = 0; j < 8; j++) idv[j] = xrow[hl + 16 * (k + j)];
#pragma unroll
            for (int j = 0; j < 8; j++) {
                float e = e127[idv[j]];
                const int i = hl + 16 * (k + j);
#pragma unroll
                for (int h = 0; h < NH; h++)
                    acc[h] = fmaf(e, ws[h * INS + i], acc[h]);
            }
        }
        float mine = 0.f;
#pragma unroll
        for (int h = 0; h < NH; h++) {
            float v = acc[h];
#pragma unroll
            for (int o = 8; o; o >>= 1)
                v += __shfl_xor_sync(0xffffffffu, v, o, 16);
            if (h == hl) mine = v;
        }
        hb = ftanh(mine + bir[hc] + bhr[hc]);
    }

    // ---- forward recurrence over 16 chunks of 8 s ----
    float wrow[NH];
#pragma unroll
    for (int j = 0; j < NH; j++) wrow[j] = whh[hc * NH + j];
    const float bias = bih[hc] + bhh[hc];

    float h = 0.f;
#pragma unroll 1
    for (int c = 0; c < 16; c++) {
        const int p = c & 1;
        if (c < 15) STAGE_LOAD(c + 1);     // loads fly during the 8 steps
        const float* sA = &stg[p][0][bslot * 96 + hc];
        const float* sB = &stg[p][1][bslot * 96 + hc];
#pragma unroll
        for (int j = 0; j < 8; j++) {
            float pb = sA[j * NH] + sB[j * NH] + bias;
            float v[NH];
#pragma unroll
            for (int k = 0; k < NH; k++)
                v[k] = __shfl_sync(0xffffffffu, h, k, 16);
            float t0 = fmaf(v[0], wrow[0], pb);
            float t1 = v[1] * wrow[1];
            float t2 = v[2] * wrow[2];
#pragma unroll
            for (int k = 3; k < NH; k += 3) {
                t0 = fmaf(v[k    ], wrow[k    ], t0);
                t1 = fmaf(v[k + 1], wrow[k + 1], t1);
                t2 = fmaf(v[k + 2], wrow[k + 2], t2);
            }
            h = ftanh(t0 + t1 + t2);
        }
        if (c < 15) STAGE_STORE(1 - p);
        __syncthreads();
    }
#undef STAGE_LOAD
#undef STAGE_STORE

    // ---- FC epilogue ----
    float v[NH], hbv[NH];
#pragma unroll
    for (int j = 0; j < NH; j++) {
        v[j]   = __shfl_sync(0xffffffffu, h,  j, 16);
        hbv[j] = __shfl_sync(0xffffffffu, hb, j, 16);
    }
    if (hl < NOUT) {
        float o = fcb[hl];
#pragma unroll
        for (int j = 0; j < NH; j++) o = fmaf(v[j], fcw[hl * 2 * NH + j], o);
#pragma unroll
        for (int j = 0; j < NH; j++) o = fmaf(hbv[j], fcw[hl * 2 * NH + NH + j], o);
        out[b * NOUT + hl] = o;
    }
}

// ---------------------------------------------------------------------------
extern "C" void kernel_launch(void* const* d_in, const int* in_sizes, int n_in,
                              void* d_out, int out_size) {
    const int*   x      = (const int*)  d_in[0];
    const float* emb    = (const float*)d_in[1];
    const float* w_ih_f = (const float*)d_in[2];
    const float* w_hh_f = (const float*)d_in[3];
    const float* b_ih_f = (const float*)d_in[4];
    const float* b_hh_f = (const float*)d_in[5];
    const float* w_ih_r = (const float*)d_in[6];
    // d_in[7] = w_hh_r (unused: reference consumes only the one-step reverse state)
    const float* b_ih_r = (const float*)d_in[8];
    const float* b_hh_r = (const float*)d_in[9];
    const float* fc_w   = (const float*)d_in[10];
    const float* fc_b   = (const float*)d_in[11];
    float* out = (float*)d_out;

    pre_kernel<<<dim3(NB / 4, 2), 128>>>(x, emb, w_ih_f);
    scan_kernel<<<NB / 8, 128>>>(x, emb, w_ih_r, b_ih_r, b_hh_r,
                                 w_hh_f, b_ih_f, b_hh_f, fc_w, fc_b, out);
}